// round 1
// baseline (speedup 1.0000x reference)
#include <cuda_runtime.h>
#include <math.h>

#define BATCH 4
#define SEQ 1024
#define DMODEL 768
#define NHEAD 12
#define DHEAD 64
#define BN (BATCH*SEQ)

// ---- scratch (static device globals; no allocation) ----
__device__ float g_q[BN * DMODEL];
__device__ float g_k[BN * DMODEL];
__device__ float g_v[BN * DMODEL];
__device__ float g_attn[(size_t)BATCH * NHEAD * SEQ * SEQ];  // 192 MB

// ============================================================
// Kernel 1: QKV projections. C = X * W, 64x64 tile, K-chunk 16.
// z = 0:q (scaled 1/8), 1:k, 2:v
// ============================================================
__global__ void qkv_gemm_kernel(const float* __restrict__ x,
                                const float* __restrict__ Wq,
                                const float* __restrict__ Wk,
                                const float* __restrict__ Wv) {
    const int z = blockIdx.z;
    const float* __restrict__ W = (z == 0) ? Wq : (z == 1) ? Wk : Wv;
    float* __restrict__ C = (z == 0) ? g_q : (z == 1) ? g_k : g_v;
    const float scale = (z == 0) ? 0.125f : 1.0f;

    const int m0 = blockIdx.y * 64;
    const int n0 = blockIdx.x * 64;

    __shared__ float As[16][64];  // [k][m]
    __shared__ float Bs[16][64];  // [k][n]

    const int t = threadIdx.x;
    const int tx = t & 15;
    const int ty = t >> 4;

    float acc[4][4] = {};

    for (int kk = 0; kk < DMODEL; kk += 16) {
#pragma unroll
        for (int i = 0; i < 4; i++) {
            int e = t + i * 256;
            int m = e >> 4, kl = e & 15;
            As[kl][m] = x[(m0 + m) * DMODEL + kk + kl];
            int kl2 = e >> 6, n = e & 63;
            Bs[kl2][n] = W[(kk + kl2) * DMODEL + n0 + n];
        }
        __syncthreads();
#pragma unroll
        for (int kl = 0; kl < 16; kl++) {
            float a[4], b[4];
#pragma unroll
            for (int i = 0; i < 4; i++) a[i] = As[kl][ty * 4 + i];
#pragma unroll
            for (int j = 0; j < 4; j++) b[j] = Bs[kl][tx * 4 + j];
#pragma unroll
            for (int i = 0; i < 4; i++)
#pragma unroll
                for (int j = 0; j < 4; j++) acc[i][j] += a[i] * b[j];
        }
        __syncthreads();
    }
#pragma unroll
    for (int i = 0; i < 4; i++)
#pragma unroll
        for (int j = 0; j < 4; j++)
            C[(m0 + ty * 4 + i) * DMODEL + n0 + tx * 4 + j] = acc[i][j] * scale;
}

// ============================================================
// Kernel 2: S[b,h,i,j] = sum_d q[b,i,h,d] * k[b,j,h,d]
// 64x64 output tile per CTA, K=64 fully in smem.
// ============================================================
__global__ void scores_kernel() {
    const int bh = blockIdx.z;
    const int b = bh / NHEAD, h = bh % NHEAD;
    const int i0 = blockIdx.y * 64;
    const int j0 = blockIdx.x * 64;

    __shared__ float Qs[64][65];
    __shared__ float Ks[64][65];

    const int t = threadIdx.x;
    const int tx = t & 15;
    const int ty = t >> 4;

    const float* qb = g_q + (size_t)(b * SEQ) * DMODEL + h * DHEAD;
    const float* kb = g_k + (size_t)(b * SEQ) * DMODEL + h * DHEAD;

    for (int e = t; e < 4096; e += 256) {
        int r = e >> 6, c = e & 63;
        Qs[r][c] = qb[(size_t)(i0 + r) * DMODEL + c];
        Ks[r][c] = kb[(size_t)(j0 + r) * DMODEL + c];
    }
    __syncthreads();

    float acc[4][4] = {};
#pragma unroll 4
    for (int d = 0; d < 64; d++) {
        float a[4], bb[4];
#pragma unroll
        for (int i = 0; i < 4; i++) a[i] = Qs[ty * 4 + i][d];
#pragma unroll
        for (int j = 0; j < 4; j++) bb[j] = Ks[tx * 4 + j][d];
#pragma unroll
        for (int i = 0; i < 4; i++)
#pragma unroll
            for (int j = 0; j < 4; j++) acc[i][j] += a[i] * bb[j];
    }

    float* Sb = g_attn + (size_t)(b * NHEAD + h) * SEQ * SEQ;
#pragma unroll
    for (int i = 0; i < 4; i++)
#pragma unroll
        for (int j = 0; j < 4; j++)
            Sb[(size_t)(i0 + ty * 4 + i) * SEQ + j0 + tx * 4 + j] = acc[i][j];
}

// ============================================================
// Kernel 3: per (b,q): softmax over k per head, theta head-mix,
// LayerNorm over k. One CTA per (b,q). Dynamic smem:
//   p[12][1024] | theta[144] | red[16]
// ============================================================
__device__ __forceinline__ float blockReduceMax(float v, float* red) {
#pragma unroll
    for (int o = 16; o; o >>= 1) v = fmaxf(v, __shfl_xor_sync(0xffffffffu, v, o));
    int w = threadIdx.x >> 5;
    if ((threadIdx.x & 31) == 0) red[w] = v;
    __syncthreads();
    if (threadIdx.x < 8) {
        v = red[threadIdx.x];
#pragma unroll
        for (int o = 4; o; o >>= 1) v = fmaxf(v, __shfl_xor_sync(0xffu, v, o));
        if (threadIdx.x == 0) red[0] = v;
    }
    __syncthreads();
    float r = red[0];
    __syncthreads();
    return r;
}

__device__ __forceinline__ float blockReduceSum(float v, float* red) {
#pragma unroll
    for (int o = 16; o; o >>= 1) v += __shfl_xor_sync(0xffffffffu, v, o);
    int w = threadIdx.x >> 5;
    if ((threadIdx.x & 31) == 0) red[w] = v;
    __syncthreads();
    if (threadIdx.x < 8) {
        v = red[threadIdx.x];
#pragma unroll
        for (int o = 4; o; o >>= 1) v += __shfl_xor_sync(0xffu, v, o);
        if (threadIdx.x == 0) red[0] = v;
    }
    __syncthreads();
    float r = red[0];
    __syncthreads();
    return r;
}

__device__ __forceinline__ float2 blockReduceSum2(float a, float b, float* red) {
#pragma unroll
    for (int o = 16; o; o >>= 1) {
        a += __shfl_xor_sync(0xffffffffu, a, o);
        b += __shfl_xor_sync(0xffffffffu, b, o);
    }
    int w = threadIdx.x >> 5;
    if ((threadIdx.x & 31) == 0) { red[w] = a; red[8 + w] = b; }
    __syncthreads();
    if (threadIdx.x < 8) {
        a = red[threadIdx.x];
        b = red[8 + threadIdx.x];
#pragma unroll
        for (int o = 4; o; o >>= 1) {
            a += __shfl_xor_sync(0xffu, a, o);
            b += __shfl_xor_sync(0xffu, b, o);
        }
        if (threadIdx.x == 0) { red[0] = a; red[8] = b; }
    }
    __syncthreads();
    float2 r = make_float2(red[0], red[8]);
    __syncthreads();
    return r;
}

__global__ void softmax_theta_ln_kernel(const float* __restrict__ theta,
                                        const float* __restrict__ lnS,
                                        const float* __restrict__ lnB) {
    extern __shared__ float sm[];
    float* p = sm;                 // 12 * 1024
    float* th = sm + NHEAD * SEQ;  // 144
    float* red = th + 144;         // 16

    const int bq = blockIdx.x;
    const int b = bq >> 10;
    const int qi = bq & 1023;
    const int t = threadIdx.x;

    // load the 12 head-rows S[b,h,qi,:]
    for (int h = 0; h < NHEAD; h++) {
        const float* src = g_attn + ((size_t)(b * NHEAD + h) * SEQ + qi) * SEQ;
#pragma unroll
        for (int e = t; e < SEQ; e += 256) p[h * SEQ + e] = src[e];
    }
    if (t < NHEAD * NHEAD) th[t] = theta[t];
    __syncthreads();

    // softmax per head (store unnormalized exp; keep 1/sum in regs)
    float inv[NHEAD];
    for (int h = 0; h < NHEAD; h++) {
        float m = -1e30f;
#pragma unroll
        for (int e = t; e < SEQ; e += 256) m = fmaxf(m, p[h * SEQ + e]);
        m = blockReduceMax(m, red);
        float s = 0.f;
#pragma unroll
        for (int e = t; e < SEQ; e += 256) {
            float ex = __expf(p[h * SEQ + e] - m);
            p[h * SEQ + e] = ex;
            s += ex;
        }
        s = blockReduceSum(s, red);
        inv[h] = 1.0f / s;
    }
    __syncthreads();

    // theta head-mix: a[i][k] = sum_h theta[h,i] * softmax[h][k], in place
#pragma unroll
    for (int e = t; e < SEQ; e += 256) {
        float ph[NHEAD];
#pragma unroll
        for (int h = 0; h < NHEAD; h++) ph[h] = p[h * SEQ + e] * inv[h];
        float a[NHEAD];
#pragma unroll
        for (int i = 0; i < NHEAD; i++) {
            float acc = 0.f;
#pragma unroll
            for (int h = 0; h < NHEAD; h++) acc += th[h * NHEAD + i] * ph[h];
            a[i] = acc;
        }
#pragma unroll
        for (int i = 0; i < NHEAD; i++) p[i * SEQ + e] = a[i];
    }
    __syncthreads();

    // LayerNorm over k per output head i, write back to g_attn
    for (int i = 0; i < NHEAD; i++) {
        float s = 0.f, s2 = 0.f;
#pragma unroll
        for (int e = t; e < SEQ; e += 256) {
            float v = p[i * SEQ + e];
            s += v;
            s2 += v * v;
        }
        float2 r2 = blockReduceSum2(s, s2, red);
        float mean = r2.x * (1.0f / SEQ);
        float var = r2.y * (1.0f / SEQ) - mean * mean;
        float rstd = rsqrtf(var + 1e-6f);
        float* dst = g_attn + ((size_t)(b * NHEAD + i) * SEQ + qi) * SEQ;
#pragma unroll
        for (int e = t; e < SEQ; e += 256)
            dst[e] = (p[i * SEQ + e] - mean) * rstd * lnS[e] + lnB[e];
    }
}

// ============================================================
// Kernel 4: out[b,k,h,d] = sum_q A[b,h,q,k] * v[b,q,h,d]
// Tile: 128 k x 64 d per CTA, q-chunk 32.
// ============================================================
__global__ void out_gemm_kernel(float* __restrict__ out) {
    const int bh = blockIdx.y;
    const int b = bh / NHEAD, h = bh % NHEAD;
    const int k0 = blockIdx.x * 128;

    __shared__ float As[32][128];  // [q][k]
    __shared__ float Vs[32][64];   // [q][d]

    const int t = threadIdx.x;
    const int tx = t & 15;   // d / 4
    const int ty = t >> 4;   // k / 8

    const float* Ab = g_attn + (size_t)(b * NHEAD + h) * SEQ * SEQ;
    const float* vb = g_v + (size_t)(b * SEQ) * DMODEL + h * DHEAD;

    float acc[8][4] = {};

    for (int q0 = 0; q0 < SEQ; q0 += 32) {
#pragma unroll
        for (int e = t; e < 4096; e += 256) {
            int r = e >> 7, c = e & 127;
            As[r][c] = Ab[(size_t)(q0 + r) * SEQ + k0 + c];
        }
#pragma unroll
        for (int e = t; e < 2048; e += 256) {
            int r = e >> 6, c = e & 63;
            Vs[r][c] = vb[(size_t)(q0 + r) * DMODEL + c];
        }
        __syncthreads();
#pragma unroll 4
        for (int qq = 0; qq < 32; qq++) {
            float a[8], bb[4];
#pragma unroll
            for (int i = 0; i < 8; i++) a[i] = As[qq][ty * 8 + i];
#pragma unroll
            for (int j = 0; j < 4; j++) bb[j] = Vs[qq][tx * 4 + j];
#pragma unroll
            for (int i = 0; i < 8; i++)
#pragma unroll
                for (int j = 0; j < 4; j++) acc[i][j] += a[i] * bb[j];
        }
        __syncthreads();
    }

#pragma unroll
    for (int i = 0; i < 8; i++)
#pragma unroll
        for (int j = 0; j < 4; j++)
            out[(size_t)(b * SEQ + k0 + ty * 8 + i) * DMODEL + h * DHEAD + tx * 4 + j] =
                acc[i][j];
}

// ============================================================
extern "C" void kernel_launch(void* const* d_in, const int* in_sizes, int n_in,
                              void* d_out, int out_size) {
    const float* x     = (const float*)d_in[0];
    const float* Wq    = (const float*)d_in[1];
    const float* Wk    = (const float*)d_in[2];
    const float* Wv    = (const float*)d_in[3];
    const float* theta = (const float*)d_in[4];
    const float* lnS   = (const float*)d_in[5];
    const float* lnB   = (const float*)d_in[6];
    float* out = (float*)d_out;

    // 1. QKV projections
    {
        dim3 grid(DMODEL / 64, BN / 64, 3);
        qkv_gemm_kernel<<<grid, 256>>>(x, Wq, Wk, Wv);
    }
    // 2. attention scores
    {
        dim3 grid(SEQ / 64, SEQ / 64, BATCH * NHEAD);
        scores_kernel<<<grid, 256>>>();
    }
    // 3. fused softmax + theta mix + LayerNorm
    {
        int smem = (NHEAD * SEQ + 144 + 16) * sizeof(float);  // ~49.8 KB
        cudaFuncSetAttribute(softmax_theta_ln_kernel,
                             cudaFuncAttributeMaxDynamicSharedMemorySize, smem);
        softmax_theta_ln_kernel<<<BATCH * SEQ, 256, smem>>>(theta, lnS, lnB);
    }
    // 4. output GEMM (A^T V with k-indexed output)
    {
        dim3 grid(SEQ / 128, BATCH * NHEAD);
        out_gemm_kernel<<<grid, 256>>>(out);
    }
}

// round 2
// speedup vs baseline: 1.9508x; 1.9508x over previous
#include <cuda_runtime.h>
#include <math.h>

#define BATCH 4
#define SEQ 1024
#define DMODEL 768
#define NHEAD 12
#define DHEAD 64
#define BN (BATCH*SEQ)

// ---- scratch (static device globals; no allocation) ----
__device__ float g_q[BN * DMODEL];
__device__ float g_k[BN * DMODEL];
__device__ float g_v[BN * DMODEL];
__device__ float g_attn[(size_t)BATCH * NHEAD * SEQ * SEQ];  // 192 MB

// ============================================================
// Kernel 1: QKV projections. C = X * W. 128x128 tile, BK=16,
// 256 threads, 8x8 microtile. z = 0:q (scaled 1/8), 1:k, 2:v
// ============================================================
__global__ __launch_bounds__(256, 2) void qkv_gemm_kernel(
    const float* __restrict__ x,
    const float* __restrict__ Wq,
    const float* __restrict__ Wk,
    const float* __restrict__ Wv) {
    const int z = blockIdx.z;
    const float* __restrict__ W = (z == 0) ? Wq : (z == 1) ? Wk : Wv;
    float* __restrict__ C = (z == 0) ? g_q : (z == 1) ? g_k : g_v;
    const float scale = (z == 0) ? 0.125f : 1.0f;

    const int m0 = blockIdx.y * 128;
    const int n0 = blockIdx.x * 128;

    __shared__ float As[16][132];  // [k][m], padded
    __shared__ float Bs[16][128];  // [k][n]

    const int t = threadIdx.x;
    const int tx = t & 15;   // n / 8
    const int ty = t >> 4;   // m / 8

    float acc[8][8] = {};

    for (int kk = 0; kk < DMODEL; kk += 16) {
#pragma unroll
        for (int i = 0; i < 2; i++) {
            int idx = t + i * 256;
            int r = idx >> 2, c = (idx & 3) * 4;
            float4 v4 = *(const float4*)(x + (size_t)(m0 + r) * DMODEL + kk + c);
            As[c + 0][r] = v4.x;
            As[c + 1][r] = v4.y;
            As[c + 2][r] = v4.z;
            As[c + 3][r] = v4.w;
            int r2 = idx >> 5, c2 = (idx & 31) * 4;
            *(float4*)(&Bs[r2][c2]) =
                *(const float4*)(W + (size_t)(kk + r2) * DMODEL + n0 + c2);
        }
        __syncthreads();
#pragma unroll
        for (int kl = 0; kl < 16; kl++) {
            float a[8], b[8];
            *(float4*)(a)     = *(const float4*)&As[kl][ty * 8];
            *(float4*)(a + 4) = *(const float4*)&As[kl][ty * 8 + 4];
            *(float4*)(b)     = *(const float4*)&Bs[kl][tx * 8];
            *(float4*)(b + 4) = *(const float4*)&Bs[kl][tx * 8 + 4];
#pragma unroll
            for (int i = 0; i < 8; i++)
#pragma unroll
                for (int j = 0; j < 8; j++) acc[i][j] += a[i] * b[j];
        }
        __syncthreads();
    }

#pragma unroll
    for (int i = 0; i < 8; i++) {
        float* dst = C + (size_t)(m0 + ty * 8 + i) * DMODEL + n0 + tx * 8;
        float4 o0 = make_float4(acc[i][0] * scale, acc[i][1] * scale,
                                acc[i][2] * scale, acc[i][3] * scale);
        float4 o1 = make_float4(acc[i][4] * scale, acc[i][5] * scale,
                                acc[i][6] * scale, acc[i][7] * scale);
        *(float4*)(dst) = o0;
        *(float4*)(dst + 4) = o1;
    }
}

// ============================================================
// Kernel 2: S[b,h,i,j] = sum_d q[b,i,h,d] * k[b,j,h,d]
// 128x128 tile, K=64 fully resident (transposed in smem),
// 256 threads, 8x8 microtile.
// ============================================================
__global__ __launch_bounds__(256, 2) void scores_kernel() {
    extern __shared__ float sm2[];
    float (*Qs)[132] = (float(*)[132])sm2;            // [d][i]
    float (*Ks)[132] = (float(*)[132])(sm2 + 64 * 132);  // [d][j]

    const int bh = blockIdx.z;
    const int b = bh / NHEAD, h = bh % NHEAD;
    const int i0 = blockIdx.y * 128;
    const int j0 = blockIdx.x * 128;

    const int t = threadIdx.x;
    const int tx = t & 15;   // j / 8
    const int ty = t >> 4;   // i / 8

    const float* qb = g_q + (size_t)b * SEQ * DMODEL + h * DHEAD;
    const float* kb = g_k + (size_t)b * SEQ * DMODEL + h * DHEAD;

    for (int e = t; e < 8192; e += 256) {
        int r = e >> 6, d = e & 63;
        Qs[d][r] = qb[(size_t)(i0 + r) * DMODEL + d];
        Ks[d][r] = kb[(size_t)(j0 + r) * DMODEL + d];
    }
    __syncthreads();

    float acc[8][8] = {};
#pragma unroll 8
    for (int d = 0; d < 64; d++) {
        float a[8], bb[8];
        *(float4*)(a)      = *(const float4*)&Qs[d][ty * 8];
        *(float4*)(a + 4)  = *(const float4*)&Qs[d][ty * 8 + 4];
        *(float4*)(bb)     = *(const float4*)&Ks[d][tx * 8];
        *(float4*)(bb + 4) = *(const float4*)&Ks[d][tx * 8 + 4];
#pragma unroll
        for (int i = 0; i < 8; i++)
#pragma unroll
            for (int j = 0; j < 8; j++) acc[i][j] += a[i] * bb[j];
    }

    float* Sb = g_attn + (size_t)(b * NHEAD + h) * SEQ * SEQ;
#pragma unroll
    for (int i = 0; i < 8; i++) {
        float* dst = Sb + (size_t)(i0 + ty * 8 + i) * SEQ + j0 + tx * 8;
        *(float4*)(dst)     = *(float4*)&acc[i][0];
        *(float4*)(dst + 4) = *(float4*)&acc[i][4];
    }
}

// ============================================================
// Kernel 3: per (b,q): softmax over k per head, theta head-mix,
// LayerNorm over k. One CTA (512 threads) per (b,q); each thread
// owns 2 consecutive k for all 12 heads, fully register-resident.
// ============================================================
#define NW3 16  // 512 threads = 16 warps

__device__ __forceinline__ void blockReduceMax12(float v[12], float* red) {
#pragma unroll
    for (int h = 0; h < 12; h++)
#pragma unroll
        for (int o = 16; o; o >>= 1)
            v[h] = fmaxf(v[h], __shfl_xor_sync(0xffffffffu, v[h], o));
    int w = threadIdx.x >> 5;
    if ((threadIdx.x & 31) == 0) {
#pragma unroll
        for (int h = 0; h < 12; h++) red[h * NW3 + w] = v[h];
    }
    __syncthreads();
#pragma unroll
    for (int h = 0; h < 12; h++) {
        float m = red[h * NW3];
#pragma unroll
        for (int w2 = 1; w2 < NW3; w2++) m = fmaxf(m, red[h * NW3 + w2]);
        v[h] = m;
    }
    __syncthreads();
}

__device__ __forceinline__ void blockReduceSum12(float v[12], float* red) {
#pragma unroll
    for (int h = 0; h < 12; h++)
#pragma unroll
        for (int o = 16; o; o >>= 1)
            v[h] += __shfl_xor_sync(0xffffffffu, v[h], o);
    int w = threadIdx.x >> 5;
    if ((threadIdx.x & 31) == 0) {
#pragma unroll
        for (int h = 0; h < 12; h++) red[h * NW3 + w] = v[h];
    }
    __syncthreads();
#pragma unroll
    for (int h = 0; h < 12; h++) {
        float m = red[h * NW3];
#pragma unroll
        for (int w2 = 1; w2 < NW3; w2++) m += red[h * NW3 + w2];
        v[h] = m;
    }
    __syncthreads();
}

__device__ __forceinline__ void blockReduceSum24(float v[24], float* red) {
#pragma unroll
    for (int h = 0; h < 24; h++)
#pragma unroll
        for (int o = 16; o; o >>= 1)
            v[h] += __shfl_xor_sync(0xffffffffu, v[h], o);
    int w = threadIdx.x >> 5;
    if ((threadIdx.x & 31) == 0) {
#pragma unroll
        for (int h = 0; h < 24; h++) red[h * NW3 + w] = v[h];
    }
    __syncthreads();
#pragma unroll
    for (int h = 0; h < 24; h++) {
        float m = red[h * NW3];
#pragma unroll
        for (int w2 = 1; w2 < NW3; w2++) m += red[h * NW3 + w2];
        v[h] = m;
    }
    __syncthreads();
}

__global__ __launch_bounds__(512) void softmax_theta_ln_kernel(
    const float* __restrict__ theta,
    const float* __restrict__ lnS,
    const float* __restrict__ lnB) {
    __shared__ float th[144];
    __shared__ float red[24 * NW3];

    const int bq = blockIdx.x;
    const int b = bq >> 10;
    const int qi = bq & 1023;
    const int t = threadIdx.x;  // owns k = 2t, 2t+1

    if (t < 144) th[t] = theta[t];

    float2 r[NHEAD];
#pragma unroll
    for (int h = 0; h < NHEAD; h++) {
        const float* src = g_attn + ((size_t)(b * NHEAD + h) * SEQ + qi) * SEQ;
        r[h] = *(const float2*)(src + 2 * t);
    }
    float2 s2v = *(const float2*)(lnS + 2 * t);
    float2 b2v = *(const float2*)(lnB + 2 * t);
    __syncthreads();

    // softmax per head
    float mx[NHEAD];
#pragma unroll
    for (int h = 0; h < NHEAD; h++) mx[h] = fmaxf(r[h].x, r[h].y);
    blockReduceMax12(mx, red);

    float sum[NHEAD];
#pragma unroll
    for (int h = 0; h < NHEAD; h++) {
        r[h].x = __expf(r[h].x - mx[h]);
        r[h].y = __expf(r[h].y - mx[h]);
        sum[h] = r[h].x + r[h].y;
    }
    blockReduceSum12(sum, red);
#pragma unroll
    for (int h = 0; h < NHEAD; h++) {
        float inv = 1.0f / sum[h];
        r[h].x *= inv;
        r[h].y *= inv;
    }

    // theta head-mix: a[i] = sum_h theta[h,i] * p[h]
    float2 a[NHEAD];
#pragma unroll
    for (int i = 0; i < NHEAD; i++) {
        float ax = 0.f, ay = 0.f;
#pragma unroll
        for (int h = 0; h < NHEAD; h++) {
            float w = th[h * NHEAD + i];
            ax += w * r[h].x;
            ay += w * r[h].y;
        }
        a[i].x = ax;
        a[i].y = ay;
    }

    // LayerNorm over k per output head i
    float st[24];
#pragma unroll
    for (int i = 0; i < NHEAD; i++) {
        st[i] = a[i].x + a[i].y;
        st[12 + i] = a[i].x * a[i].x + a[i].y * a[i].y;
    }
    blockReduceSum24(st, red);

#pragma unroll
    for (int i = 0; i < NHEAD; i++) {
        float mean = st[i] * (1.0f / SEQ);
        float var = st[12 + i] * (1.0f / SEQ) - mean * mean;
        float rstd = rsqrtf(var + 1e-6f);
        float* dst = g_attn + ((size_t)(b * NHEAD + i) * SEQ + qi) * SEQ;
        float2 o;
        o.x = (a[i].x - mean) * rstd * s2v.x + b2v.x;
        o.y = (a[i].y - mean) * rstd * s2v.y + b2v.y;
        *(float2*)(dst + 2 * t) = o;
    }
}

// ============================================================
// Kernel 4: out[b,k,h,d] = sum_q A[b,h,q,k] * v[b,q,h,d]
// 128k x 64d tile, 128 threads, 8x8 microtile, q-chunk 16.
// ============================================================
__global__ __launch_bounds__(128) void out_gemm_kernel(float* __restrict__ out) {
    const int bh = blockIdx.y;
    const int b = bh / NHEAD, h = bh % NHEAD;
    const int k0 = blockIdx.x * 128;

    __shared__ float As[16][128];  // [q][k]
    __shared__ float Vs[16][64];   // [q][d]

    const int t = threadIdx.x;
    const int tx = t & 7;    // d / 8
    const int ty = t >> 3;   // k / 8 (0..15)

    const float* Ab = g_attn + (size_t)(b * NHEAD + h) * SEQ * SEQ;
    const float* vb = g_v + (size_t)b * SEQ * DMODEL + h * DHEAD;

    float acc[8][8] = {};

    for (int q0 = 0; q0 < SEQ; q0 += 16) {
#pragma unroll
        for (int i = 0; i < 4; i++) {
            int idx = t + i * 128;
            int r = idx >> 5, c = (idx & 31) * 4;
            *(float4*)(&As[r][c]) =
                *(const float4*)(Ab + (size_t)(q0 + r) * SEQ + k0 + c);
        }
#pragma unroll
        for (int i = 0; i < 2; i++) {
            int idx = t + i * 128;
            int r = idx >> 4, c = (idx & 15) * 4;
            *(float4*)(&Vs[r][c]) =
                *(const float4*)(vb + (size_t)(q0 + r) * DMODEL + c);
        }
        __syncthreads();
#pragma unroll
        for (int qq = 0; qq < 16; qq++) {
            float a[8], bb[8];
            *(float4*)(a)      = *(const float4*)&As[qq][ty * 8];
            *(float4*)(a + 4)  = *(const float4*)&As[qq][ty * 8 + 4];
            *(float4*)(bb)     = *(const float4*)&Vs[qq][tx * 8];
            *(float4*)(bb + 4) = *(const float4*)&Vs[qq][tx * 8 + 4];
#pragma unroll
            for (int i = 0; i < 8; i++)
#pragma unroll
                for (int j = 0; j < 8; j++) acc[i][j] += a[i] * bb[j];
        }
        __syncthreads();
    }

#pragma unroll
    for (int i = 0; i < 8; i++) {
        float* dst = out + (size_t)(b * SEQ + k0 + ty * 8 + i) * DMODEL + h * DHEAD + tx * 8;
        *(float4*)(dst)     = *(float4*)&acc[i][0];
        *(float4*)(dst + 4) = *(float4*)&acc[i][4];
    }
}

// ============================================================
extern "C" void kernel_launch(void* const* d_in, const int* in_sizes, int n_in,
                              void* d_out, int out_size) {
    const float* x     = (const float*)d_in[0];
    const float* Wq    = (const float*)d_in[1];
    const float* Wk    = (const float*)d_in[2];
    const float* Wv    = (const float*)d_in[3];
    const float* theta = (const float*)d_in[4];
    const float* lnS   = (const float*)d_in[5];
    const float* lnB   = (const float*)d_in[6];
    float* out = (float*)d_out;

    // 1. QKV projections
    {
        dim3 grid(DMODEL / 128, BN / 128, 3);
        qkv_gemm_kernel<<<grid, 256>>>(x, Wq, Wk, Wv);
    }
    // 2. attention scores
    {
        int smem = 2 * 64 * 132 * sizeof(float);  // 67.6 KB
        cudaFuncSetAttribute(scores_kernel,
                             cudaFuncAttributeMaxDynamicSharedMemorySize, smem);
        dim3 grid(SEQ / 128, SEQ / 128, BATCH * NHEAD);
        scores_kernel<<<grid, 256, smem>>>();
    }
    // 3. fused softmax + theta mix + LayerNorm (register-resident)
    {
        softmax_theta_ln_kernel<<<BATCH * SEQ, 512>>>(theta, lnS, lnB);
    }
    // 4. output GEMM (A^T V with k-indexed output)
    {
        dim3 grid(SEQ / 128, BATCH * NHEAD);
        out_gemm_kernel<<<grid, 128>>>(out);
    }
}